// round 1
// baseline (speedup 1.0000x reference)
#include <cuda_runtime.h>

// Retina glimpse: x [B=16384, C=3, 32, 32] f32, l [B,2] f32 in [-1,1].
// Outputs concatenated into d_out:
//   full  [B,3,32,32] : x masked to the valid part of the 16x16 window, else 0
//   patch [B,3,16,16] : gathered window, 0 where out of [0,32) bounds
//
// Per sample: coord = (int)(0.5f*((clamp(l,-1,1)+1)*32)); start = coord - 8.

#define BB 16384
#define CC 3
#define HH 32
#define GG 16
#define FULL_PER_B (CC*HH*HH)   // 3072 floats
#define PATCH_PER_B (CC*GG*GG)  // 768 floats

__global__ __launch_bounds__(256) void retina_kernel(
    const float* __restrict__ x,
    const float* __restrict__ l,
    float* __restrict__ full,
    float* __restrict__ patch)
{
    const int b = blockIdx.x;
    __shared__ int s_rs, s_cs;
    if (threadIdx.x == 0) {
        float l0 = fminf(fmaxf(l[2 * b + 0], -1.0f), 1.0f);
        float l1 = fminf(fmaxf(l[2 * b + 1], -1.0f), 1.0f);
        // match reference op order: (0.5 * ((l + 1.0) * H)) then trunc-to-int
        int r = (int)(0.5f * ((l0 + 1.0f) * 32.0f));
        int c = (int)(0.5f * ((l1 + 1.0f) * 32.0f));
        s_rs = r - GG / 2;
        s_cs = c - GG / 2;
    }
    __syncthreads();
    const int rs = s_rs;
    const int cs = s_cs;

    const float* xb = x + (size_t)b * FULL_PER_B;
    float* fb = full + (size_t)b * FULL_PER_B;

    // ---- full: 3072 floats = 768 float4 per sample; 3 per thread ----
    #pragma unroll
    for (int iter = 0; iter < 3; ++iter) {
        int v = iter * 256 + threadIdx.x;   // [0,768) float4 index
        int ch  = v >> 8;                   // channel (256 float4 per channel)
        int rem = v & 255;
        int h   = rem >> 3;                 // row (8 float4 per 32-col row)
        int w0  = (rem & 7) << 2;           // first column of this float4
        float4 out = make_float4(0.f, 0.f, 0.f, 0.f);
        bool rowin = (h >= rs) && (h < rs + GG);
        if (rowin && (w0 + 3 >= cs) && (w0 <= cs + GG - 1)) {
            float4 xv = *(const float4*)(xb + (ch << 10) + (h << 5) + w0);
            out.x = (w0 + 0 >= cs && w0 + 0 < cs + GG) ? xv.x : 0.f;
            out.y = (w0 + 1 >= cs && w0 + 1 < cs + GG) ? xv.y : 0.f;
            out.z = (w0 + 2 >= cs && w0 + 2 < cs + GG) ? xv.z : 0.f;
            out.w = (w0 + 3 >= cs && w0 + 3 < cs + GG) ? xv.w : 0.f;
        }
        *(float4*)(fb + ((size_t)v << 2)) = out;
    }

    // ---- patch: 768 floats per sample; 3 per thread, coalesced stores ----
    float* pb = patch + (size_t)b * PATCH_PER_B;
    #pragma unroll
    for (int iter = 0; iter < 3; ++iter) {
        int e = iter * 256 + threadIdx.x;   // [0,768)
        int ch  = e >> 8;
        int rem = e & 255;
        int i   = rem >> 4;
        int j   = rem & 15;
        int row = rs + i;
        int col = cs + j;
        float vv = 0.f;
        if (row >= 0 && row < 32 && col >= 0 && col < 32)
            vv = xb[(ch << 10) + (row << 5) + col];
        pb[e] = vv;
    }
}

extern "C" void kernel_launch(void* const* d_in, const int* in_sizes, int n_in,
                              void* d_out, int out_size)
{
    const float* x = (const float*)d_in[0];   // [16384,3,32,32]
    const float* l = (const float*)d_in[1];   // [16384,2]
    float* full  = (float*)d_out;
    float* patch = (float*)d_out + (size_t)BB * FULL_PER_B;
    retina_kernel<<<BB, 256>>>(x, l, full, patch);
}